// round 11
// baseline (speedup 1.0000x reference)
#include <cuda_runtime.h>
#include <cuda_bf16.h>
#include <mma.h>
#include <cstdint>
#include <cstddef>
#include <math.h>

using namespace nvcuda;

#define B_   2
#define S_   2048
#define NH   32
#define NKV  8
#define HD   128
#define HID  4096

// ---------------- scratch (device globals; no allocations) ----------------
__device__ float g_qlin[B_ * S_ * HID];
__device__ float g_klin[B_ * S_ * NKV * HD];
__device__ float g_vlin[B_ * S_ * NKV * HD];
__device__ float g_q[B_ * NH * S_ * HD];
__device__ float g_k[B_ * NKV * S_ * HD];
__device__ float g_v[B_ * NKV * S_ * HD];
__device__ float g_attn[B_ * S_ * HID];

__device__ __nv_bfloat16 g_xh[B_ * S_ * HID];
__device__ __nv_bfloat16 g_xl[B_ * S_ * HID];
__device__ __nv_bfloat16 g_wqh[HID * HID];
__device__ __nv_bfloat16 g_wql[HID * HID];
__device__ __nv_bfloat16 g_wkh[NKV * HD * HID];
__device__ __nv_bfloat16 g_wkl[NKV * HD * HID];
__device__ __nv_bfloat16 g_wvh[NKV * HD * HID];
__device__ __nv_bfloat16 g_wvl[NKV * HD * HID];
__device__ __nv_bfloat16 g_woh[HID * HID];
__device__ __nv_bfloat16 g_wol[HID * HID];
__device__ __nv_bfloat16 g_ah[B_ * S_ * HID];
__device__ __nv_bfloat16 g_al[B_ * S_ * HID];

// ---------------- cp.async helpers ----------------------------------------
__device__ __forceinline__ uint32_t smem_u32(const void* p) {
    return (uint32_t)__cvta_generic_to_shared(p);
}
__device__ __forceinline__ void cp_async16(uint32_t saddr, const void* gptr) {
    asm volatile("cp.async.cg.shared.global [%0], [%1], 16;" :: "r"(saddr), "l"(gptr));
}
__device__ __forceinline__ void cp_commit() {
    asm volatile("cp.async.commit_group;" ::: "memory");
}
__device__ __forceinline__ void cp_wait1() {
    asm volatile("cp.async.wait_group 1;" ::: "memory");
}
__device__ __forceinline__ void cp_wait0() {
    asm volatile("cp.async.wait_group 0;" ::: "memory");
}

// ================= fp32 -> (bf16 hi, bf16 lo) split ========================
__global__ void cvt_split(const float* __restrict__ in,
                          __nv_bfloat16* __restrict__ hi,
                          __nv_bfloat16* __restrict__ lo, int n4)
{
    int i = blockIdx.x * blockDim.x + threadIdx.x;
    if (i >= n4) return;
    float4 f = ((const float4*)in)[i];
    __nv_bfloat16 h0 = __float2bfloat16(f.x);
    __nv_bfloat16 h1 = __float2bfloat16(f.y);
    __nv_bfloat16 h2 = __float2bfloat16(f.z);
    __nv_bfloat16 h3 = __float2bfloat16(f.w);
    __nv_bfloat162 ha; ha.x = h0; ha.y = h1;
    __nv_bfloat162 hb; hb.x = h2; hb.y = h3;
    ((__nv_bfloat162*)hi)[2 * i + 0] = ha;
    ((__nv_bfloat162*)hi)[2 * i + 1] = hb;
    __nv_bfloat162 la;
    __nv_bfloat162 lb;
    la.x = __float2bfloat16(f.x - __bfloat162float(h0));
    la.y = __float2bfloat16(f.y - __bfloat162float(h1));
    lb.x = __float2bfloat16(f.z - __bfloat162float(h2));
    lb.y = __float2bfloat16(f.w - __bfloat162float(h3));
    ((__nv_bfloat162*)lo)[2 * i + 0] = la;
    ((__nv_bfloat162*)lo)[2 * i + 1] = lb;
}

// ================= wmma bf16 split GEMM, cp.async double-buffered ==========
// C[M,N] = A[M,K] @ B[N,K]^T via 3-term split (AhBh + AhBl + AlBh).
// Block tile 128x128x32, 8 warps (2x4), warp tile 64x32 (4x2 wmma frags).
#define W_PAD 40
#define T_ELEM (128 * W_PAD)                 // elements per tile buffer
#define STAGE_ELEM (4 * T_ELEM)              // Ah, Al, Bh, Bl
#define G2_SMEM (2 * STAGE_ELEM * 2)         // bytes (bf16)

__global__ __launch_bounds__(256) void gemm_wmma(
    const __nv_bfloat16* __restrict__ Ah, const __nv_bfloat16* __restrict__ Al,
    const __nv_bfloat16* __restrict__ Bh, const __nv_bfloat16* __restrict__ Bl,
    float* __restrict__ C, int M, int N, int K)
{
    extern __shared__ __align__(16) __nv_bfloat16 smem[];

    const int tid = threadIdx.x;
    const int wid = tid >> 5;
    const int wm = wid >> 2;      // 0..1
    const int wn = wid & 3;       // 0..3
    const int m0 = blockIdx.y * 128;
    const int n0 = blockIdx.x * 128;

    // per-thread load slots: 2 iterations x (row, col) per tile
    const int lr0 = tid >> 2;              // rows 0..63
    const int lc  = (tid & 3) * 8;         // cols 0,8,16,24

    wmma::fragment<wmma::accumulator, 16, 16, 16, float> acc[4][2];
#pragma unroll
    for (int i = 0; i < 4; i++)
#pragma unroll
        for (int j = 0; j < 2; j++)
            wmma::fill_fragment(acc[i][j], 0.0f);

    const int NK = K >> 5;   // BK = 32

    // ---- issue stage 0 ----
    {
        __nv_bfloat16* st = smem;
#pragma unroll
        for (int half = 0; half < 2; half++) {
            int row = lr0 + half * 64;
            uint32_t so = (uint32_t)(row * W_PAD + lc) * 2;
            const size_t ga = (size_t)(m0 + row) * K + lc;
            const size_t gb = (size_t)(n0 + row) * K + lc;
            cp_async16(smem_u32(st) + so,              Ah + ga);
            cp_async16(smem_u32(st + T_ELEM) + so,     Al + ga);
            cp_async16(smem_u32(st + 2 * T_ELEM) + so, Bh + gb);
            cp_async16(smem_u32(st + 3 * T_ELEM) + so, Bl + gb);
        }
        cp_commit();
    }

    for (int kt = 0; kt < NK; kt++) {
        // ---- prefetch next stage ----
        if (kt + 1 < NK) {
            __nv_bfloat16* st = smem + ((kt + 1) & 1) * STAGE_ELEM;
            const int koff = (kt + 1) << 5;
#pragma unroll
            for (int half = 0; half < 2; half++) {
                int row = lr0 + half * 64;
                uint32_t so = (uint32_t)(row * W_PAD + lc) * 2;
                const size_t ga = (size_t)(m0 + row) * K + koff + lc;
                const size_t gb = (size_t)(n0 + row) * K + koff + lc;
                cp_async16(smem_u32(st) + so,              Ah + ga);
                cp_async16(smem_u32(st + T_ELEM) + so,     Al + ga);
                cp_async16(smem_u32(st + 2 * T_ELEM) + so, Bh + gb);
                cp_async16(smem_u32(st + 3 * T_ELEM) + so, Bl + gb);
            }
            cp_commit();
            cp_wait1();
        } else {
            cp_wait0();
        }
        __syncthreads();

        const __nv_bfloat16* sAh = smem + (kt & 1) * STAGE_ELEM;
        const __nv_bfloat16* sAl = sAh + T_ELEM;
        const __nv_bfloat16* sBh = sAh + 2 * T_ELEM;
        const __nv_bfloat16* sBl = sAh + 3 * T_ELEM;

#pragma unroll
        for (int kk = 0; kk < 32; kk += 16) {
            wmma::fragment<wmma::matrix_a, 16, 16, 16, __nv_bfloat16, wmma::row_major> fah[4];
            wmma::fragment<wmma::matrix_a, 16, 16, 16, __nv_bfloat16, wmma::row_major> fal[4];
            wmma::fragment<wmma::matrix_b, 16, 16, 16, __nv_bfloat16, wmma::col_major> fbh[2];
            wmma::fragment<wmma::matrix_b, 16, 16, 16, __nv_bfloat16, wmma::col_major> fbl[2];
#pragma unroll
            for (int i = 0; i < 4; i++) {
                wmma::load_matrix_sync(fah[i], &sAh[(wm * 64 + i * 16) * W_PAD + kk], W_PAD);
                wmma::load_matrix_sync(fal[i], &sAl[(wm * 64 + i * 16) * W_PAD + kk], W_PAD);
            }
#pragma unroll
            for (int j = 0; j < 2; j++) {
                wmma::load_matrix_sync(fbh[j], &sBh[(wn * 32 + j * 16) * W_PAD + kk], W_PAD);
                wmma::load_matrix_sync(fbl[j], &sBl[(wn * 32 + j * 16) * W_PAD + kk], W_PAD);
            }
#pragma unroll
            for (int i = 0; i < 4; i++) {
#pragma unroll
                for (int j = 0; j < 2; j++) {
                    wmma::mma_sync(acc[i][j], fah[i], fbh[j], acc[i][j]);
                    wmma::mma_sync(acc[i][j], fah[i], fbl[j], acc[i][j]);
                    wmma::mma_sync(acc[i][j], fal[i], fbh[j], acc[i][j]);
                }
            }
        }
        __syncthreads();
    }

#pragma unroll
    for (int i = 0; i < 4; i++) {
#pragma unroll
        for (int j = 0; j < 2; j++) {
            float* dst = C + (size_t)(m0 + wm * 64 + i * 16) * N + n0 + wn * 32 + j * 16;
            wmma::store_matrix_sync(dst, acc[i][j], N, wmma::mem_row_major);
        }
    }
}

// -------- RoPE + transpose: in [B*S, nh*128] -> out [B, nh, S, 128] -------
__global__ void rope_perm(const float* __restrict__ in, float* __restrict__ outp,
                          int nheads)
{
    int idx = blockIdx.x * blockDim.x + threadIdx.x;
    int total = B_ * S_ * nheads * 64;
    if (idx >= total) return;
    int i = idx & 63;
    int t = idx >> 6;
    int h = t % nheads; t /= nheads;
    int s = t % S_;
    int b = t / S_;
    const float* src = in + ((b * S_ + s) * nheads + h) * HD;
    float x1 = src[i];
    float x2 = src[i + 64];
    float inv = __expf(-(float)i * 0.14391156831212790f);
    float ang = (float)s * inv;
    float sn, cs;
    sincosf(ang, &sn, &cs);
    float* dst = outp + ((b * nheads + h) * S_ + s) * HD;
    dst[i]      = x1 * cs - x2 * sn;
    dst[i + 64] = x2 * cs + x1 * sn;
}

// -------- V transpose: [B*S, 8*128] -> [B, 8, S, 128] ---------------------
__global__ void perm_v(const float* __restrict__ in, float* __restrict__ outp)
{
    int idx = blockIdx.x * blockDim.x + threadIdx.x;
    int total = B_ * S_ * NKV * HD;
    if (idx >= total) return;
    int d = idx & 127;
    int t = idx >> 7;
    int kh = t % NKV; t /= NKV;
    int s = t % S_;
    int b = t / S_;
    outp[((b * NKV + kh) * S_ + s) * HD + d] =
        in[((b * S_ + s) * NKV + kh) * HD + d];
}

// -------- fp32 flash attention (Round-1 verbatim) -------------------------
#define QS_STRIDE 132
#define PS_STRIDE 68
#define FLASH_SMEM_FLOATS (64*QS_STRIDE + 128*64 + 64*128 + 64*PS_STRIDE)

__global__ __launch_bounds__(256) void flash_attn(
    const float* __restrict__ q, const float* __restrict__ k,
    const float* __restrict__ v, float* __restrict__ outp)
{
    const int qt = blockIdx.x;
    const int bh = blockIdx.y;
    const int b  = bh >> 5;
    const int h  = bh & 31;
    const int kh = h >> 2;
    const int q0 = qt * 64;

    extern __shared__ float sm[];
    float* Qs = sm;
    float* Kt = Qs + 64 * QS_STRIDE;
    float* Vs = Kt + 128 * 64;
    float* Ps = Vs + 64 * 128;

    const int tid = threadIdx.x;
    const int r = tid >> 2;
    const int g = tid & 3;
    const float scale = 0.08838834764831845f;

    const float* qb = q + ((b * NH + h) * S_ + q0) * HD;
#pragma unroll
    for (int p = 0; p < 8; p++) {
        int idx = tid + p * 256;
        int row = idx >> 5;
        int cc = (idx & 31) * 4;
        float4 f = *(const float4*)&qb[row * HD + cc];
        Qs[row * QS_STRIDE + cc + 0] = f.x * scale;
        Qs[row * QS_STRIDE + cc + 1] = f.y * scale;
        Qs[row * QS_STRIDE + cc + 2] = f.z * scale;
        Qs[row * QS_STRIDE + cc + 3] = f.w * scale;
    }

    float O[32];
#pragma unroll
    for (int i = 0; i < 32; i++) O[i] = 0.f;
    float mrow = -1e30f, lrow = 0.f;

    const float* kbase = k + (b * NKV + kh) * S_ * HD;
    const float* vbase = v + (b * NKV + kh) * S_ * HD;
    const int nkb = qt + 1;

    for (int kb = 0; kb < nkb; kb++) {
        __syncthreads();
        const float* kp = kbase + kb * 64 * HD;
        const float* vp = vbase + kb * 64 * HD;
#pragma unroll
        for (int p = 0; p < 8; p++) {
            int idx = tid + p * 256;
            int row = idx >> 5;
            int cc = (idx & 31) * 4;
            float4 f = *(const float4*)&kp[row * HD + cc];
            Kt[(cc + 0) * 64 + row] = f.x;
            Kt[(cc + 1) * 64 + row] = f.y;
            Kt[(cc + 2) * 64 + row] = f.z;
            Kt[(cc + 3) * 64 + row] = f.w;
            float4 fv = *(const float4*)&vp[row * HD + cc];
            *(float4*)&Vs[row * HD + cc] = fv;
        }
        __syncthreads();

        float s[16];
#pragma unroll
        for (int jj = 0; jj < 16; jj++) s[jj] = 0.f;
#pragma unroll 1
        for (int dc = 0; dc < 8; dc++) {
            float qr[16];
            *(float4*)&qr[0]  = *(const float4*)&Qs[r * QS_STRIDE + dc * 16 + 0];
            *(float4*)&qr[4]  = *(const float4*)&Qs[r * QS_STRIDE + dc * 16 + 4];
            *(float4*)&qr[8]  = *(const float4*)&Qs[r * QS_STRIDE + dc * 16 + 8];
            *(float4*)&qr[12] = *(const float4*)&Qs[r * QS_STRIDE + dc * 16 + 12];
#pragma unroll
            for (int dd = 0; dd < 16; dd++) {
                const int d = dc * 16 + dd;
                const float* krow = &Kt[d * 64 + g * 16];
                float4 k0 = *(const float4*)&krow[0];
                float4 k1 = *(const float4*)&krow[4];
                float4 k2 = *(const float4*)&krow[8];
                float4 k3 = *(const float4*)&krow[12];
                float qv = qr[dd];
                s[0]  = fmaf(qv, k0.x, s[0]);  s[1]  = fmaf(qv, k0.y, s[1]);
                s[2]  = fmaf(qv, k0.z, s[2]);  s[3]  = fmaf(qv, k0.w, s[3]);
                s[4]  = fmaf(qv, k1.x, s[4]);  s[5]  = fmaf(qv, k1.y, s[5]);
                s[6]  = fmaf(qv, k1.z, s[6]);  s[7]  = fmaf(qv, k1.w, s[7]);
                s[8]  = fmaf(qv, k2.x, s[8]);  s[9]  = fmaf(qv, k2.y, s[9]);
                s[10] = fmaf(qv, k2.z, s[10]); s[11] = fmaf(qv, k2.w, s[11]);
                s[12] = fmaf(qv, k3.x, s[12]); s[13] = fmaf(qv, k3.y, s[13]);
                s[14] = fmaf(qv, k3.z, s[14]); s[15] = fmaf(qv, k3.w, s[15]);
            }
        }

        if (kb == qt) {
            const int qi = q0 + r;
#pragma unroll
            for (int jj = 0; jj < 16; jj++) {
                int kj = kb * 64 + g * 16 + jj;
                if (kj > qi) s[jj] = -1e30f;
            }
        }

        float mx = s[0];
#pragma unroll
        for (int jj = 1; jj < 16; jj++) mx = fmaxf(mx, s[jj]);
        mx = fmaxf(mx, __shfl_xor_sync(0xffffffffu, mx, 1));
        mx = fmaxf(mx, __shfl_xor_sync(0xffffffffu, mx, 2));
        float mnew = fmaxf(mrow, mx);
        float corr = __expf(mrow - mnew);
        float rs = 0.f;
#pragma unroll
        for (int jj = 0; jj < 16; jj++) {
            float pv = __expf(s[jj] - mnew);
            s[jj] = pv;
            rs += pv;
        }
        rs += __shfl_xor_sync(0xffffffffu, rs, 1);
        rs += __shfl_xor_sync(0xffffffffu, rs, 2);
        lrow = lrow * corr + rs;
        mrow = mnew;
#pragma unroll
        for (int i = 0; i < 32; i++) O[i] *= corr;

        *(float4*)&Ps[r * PS_STRIDE + g * 16 + 0]  = make_float4(s[0], s[1], s[2], s[3]);
        *(float4*)&Ps[r * PS_STRIDE + g * 16 + 4]  = make_float4(s[4], s[5], s[6], s[7]);
        *(float4*)&Ps[r * PS_STRIDE + g * 16 + 8]  = make_float4(s[8], s[9], s[10], s[11]);
        *(float4*)&Ps[r * PS_STRIDE + g * 16 + 12] = make_float4(s[12], s[13], s[14], s[15]);
        __syncwarp();

#pragma unroll 4
        for (int jj = 0; jj < 64; jj++) {
            float pv = Ps[r * PS_STRIDE + jj];
            const float* vrow = &Vs[jj * HD + g * 4];
#pragma unroll
            for (int ii = 0; ii < 8; ii++) {
                float4 vv = *(const float4*)&vrow[ii * 16];
                O[ii * 4 + 0] = fmaf(pv, vv.x, O[ii * 4 + 0]);
                O[ii * 4 + 1] = fmaf(pv, vv.y, O[ii * 4 + 1]);
                O[ii * 4 + 2] = fmaf(pv, vv.z, O[ii * 4 + 2]);
                O[ii * 4 + 3] = fmaf(pv, vv.w, O[ii * 4 + 3]);
            }
        }
    }

    const float inv = 1.0f / lrow;
    float* ob = outp + (b * S_ + q0 + r) * HID + h * HD + g * 4;
#pragma unroll
    for (int ii = 0; ii < 8; ii++) {
        float4 vv = make_float4(O[ii * 4 + 0] * inv, O[ii * 4 + 1] * inv,
                                O[ii * 4 + 2] * inv, O[ii * 4 + 3] * inv);
        *(float4*)&ob[ii * 16] = vv;
    }
}

// ---------------- launch ---------------------------------------------------
extern "C" void kernel_launch(void* const* d_in, const int* in_sizes, int n_in,
                              void* d_out, int out_size)
{
    (void)in_sizes; (void)n_in; (void)out_size;
    const float* x  = (const float*)d_in[0];
    const float* wq = (const float*)d_in[2];
    const float* wk = (const float*)d_in[3];
    const float* wv = (const float*)d_in[4];
    const float* wo = (const float*)d_in[5];
    float* out = (float*)d_out;

    float *qlin, *klin, *vlin, *qb, *kb, *vb, *attn;
    cudaGetSymbolAddress((void**)&qlin, g_qlin);
    cudaGetSymbolAddress((void**)&klin, g_klin);
    cudaGetSymbolAddress((void**)&vlin, g_vlin);
    cudaGetSymbolAddress((void**)&qb,   g_q);
    cudaGetSymbolAddress((void**)&kb,   g_k);
    cudaGetSymbolAddress((void**)&vb,   g_v);
    cudaGetSymbolAddress((void**)&attn, g_attn);

    __nv_bfloat16 *xh, *xl, *wqh, *wql, *wkh, *wkl, *wvh, *wvl, *woh, *wol, *ah, *al;
    cudaGetSymbolAddress((void**)&xh,  g_xh);
    cudaGetSymbolAddress((void**)&xl,  g_xl);
    cudaGetSymbolAddress((void**)&wqh, g_wqh);
    cudaGetSymbolAddress((void**)&wql, g_wql);
    cudaGetSymbolAddress((void**)&wkh, g_wkh);
    cudaGetSymbolAddress((void**)&wkl, g_wkl);
    cudaGetSymbolAddress((void**)&wvh, g_wvh);
    cudaGetSymbolAddress((void**)&wvl, g_wvl);
    cudaGetSymbolAddress((void**)&woh, g_woh);
    cudaGetSymbolAddress((void**)&wol, g_wol);
    cudaGetSymbolAddress((void**)&ah,  g_ah);
    cudaGetSymbolAddress((void**)&al,  g_al);

    const int M = B_ * S_;
    const int NKVD = NKV * HD;

    int n4 = (M * HID) / 4;
    cvt_split<<<(n4 + 255) / 256, 256>>>(x,  xh,  xl,  n4);
    cvt_split<<<(n4 + 255) / 256, 256>>>(wq, wqh, wql, n4);
    cvt_split<<<(n4 + 255) / 256, 256>>>(wo, woh, wol, n4);
    int n4s = (NKVD * HID) / 4;
    cvt_split<<<(n4s + 255) / 256, 256>>>(wk, wkh, wkl, n4s);
    cvt_split<<<(n4s + 255) / 256, 256>>>(wv, wvh, wvl, n4s);

    cudaFuncSetAttribute(gemm_wmma, cudaFuncAttributeMaxDynamicSharedMemorySize, G2_SMEM);

    gemm_wmma<<<dim3(HID / 128, M / 128), 256, G2_SMEM>>>(xh, xl, wqh, wql, qlin, M, HID, HID);
    gemm_wmma<<<dim3(NKVD / 128, M / 128), 256, G2_SMEM>>>(xh, xl, wkh, wkl, klin, M, NKVD, HID);
    gemm_wmma<<<dim3(NKVD / 128, M / 128), 256, G2_SMEM>>>(xh, xl, wvh, wvl, vlin, M, NKVD, HID);

    int n1 = B_ * S_ * NH * 64;
    rope_perm<<<(n1 + 255) / 256, 256>>>(qlin, qb, NH);
    int n2 = B_ * S_ * NKV * 64;
    rope_perm<<<(n2 + 255) / 256, 256>>>(klin, kb, NKV);
    int n3 = B_ * S_ * NKV * HD;
    perm_v<<<(n3 + 255) / 256, 256>>>(vlin, vb);

    const int flash_smem = FLASH_SMEM_FLOATS * (int)sizeof(float);
    cudaFuncSetAttribute(flash_attn, cudaFuncAttributeMaxDynamicSharedMemorySize,
                         flash_smem);
    flash_attn<<<dim3(S_ / 64, B_ * NH), 256, flash_smem>>>(qb, kb, vb, attn);

    cvt_split<<<(n4 + 255) / 256, 256>>>(attn, ah, al, n4);

    gemm_wmma<<<dim3(HID / 128, M / 128), 256, G2_SMEM>>>(ah, al, woh, wol, out, M, HID, HID);
}

// round 12
// speedup vs baseline: 1.4557x; 1.4557x over previous
#include <cuda_runtime.h>
#include <cuda_bf16.h>
#include <mma.h>
#include <cstdint>
#include <cstddef>
#include <math.h>

using namespace nvcuda;

#define B_   2
#define S_   2048
#define NH   32
#define NKV  8
#define HD   128
#define HID  4096

// ---------------- scratch (device globals; no allocations) ----------------
__device__ float g_qlin[B_ * S_ * HID];
__device__ float g_klin[B_ * S_ * NKV * HD];
__device__ float g_vlin[B_ * S_ * NKV * HD];
__device__ float g_q[B_ * NH * S_ * HD];
__device__ float g_k[B_ * NKV * S_ * HD];
__device__ float g_v[B_ * NKV * S_ * HD];
__device__ float g_attn[B_ * S_ * HID];

__device__ __nv_bfloat16 g_xh[B_ * S_ * HID];
__device__ __nv_bfloat16 g_xl[B_ * S_ * HID];
__device__ __nv_bfloat16 g_wqh[HID * HID];
__device__ __nv_bfloat16 g_wql[HID * HID];
__device__ __nv_bfloat16 g_wkh[NKV * HD * HID];
__device__ __nv_bfloat16 g_wkl[NKV * HD * HID];
__device__ __nv_bfloat16 g_wvh[NKV * HD * HID];
__device__ __nv_bfloat16 g_wvl[NKV * HD * HID];
__device__ __nv_bfloat16 g_woh[HID * HID];
__device__ __nv_bfloat16 g_wol[HID * HID];
__device__ __nv_bfloat16 g_ah[B_ * S_ * HID];
__device__ __nv_bfloat16 g_al[B_ * S_ * HID];

// ================= fp32 -> (bf16 hi, bf16 lo) split ========================
__global__ void cvt_split(const float* __restrict__ in,
                          __nv_bfloat16* __restrict__ hi,
                          __nv_bfloat16* __restrict__ lo, int n4)
{
    int i = blockIdx.x * blockDim.x + threadIdx.x;
    if (i >= n4) return;
    float4 f = ((const float4*)in)[i];
    __nv_bfloat16 h0 = __float2bfloat16(f.x);
    __nv_bfloat16 h1 = __float2bfloat16(f.y);
    __nv_bfloat16 h2 = __float2bfloat16(f.z);
    __nv_bfloat16 h3 = __float2bfloat16(f.w);
    __nv_bfloat162 ha; ha.x = h0; ha.y = h1;
    __nv_bfloat162 hb; hb.x = h2; hb.y = h3;
    ((__nv_bfloat162*)hi)[2 * i + 0] = ha;
    ((__nv_bfloat162*)hi)[2 * i + 1] = hb;
    __nv_bfloat162 la;
    __nv_bfloat162 lb;
    la.x = __float2bfloat16(f.x - __bfloat162float(h0));
    la.y = __float2bfloat16(f.y - __bfloat162float(h1));
    lb.x = __float2bfloat16(f.z - __bfloat162float(h2));
    lb.y = __float2bfloat16(f.w - __bfloat162float(h3));
    ((__nv_bfloat162*)lo)[2 * i + 0] = la;
    ((__nv_bfloat162*)lo)[2 * i + 1] = lb;
}

// ================= wmma bf16 split GEMM, register-prefetch pipelined =======
// C[M,N] = A[M,K] @ B[N,K]^T via 3-term split (AhBh + AhBl + AlBh).
// Block tile 128x128x32, 8 warps (2x4), warp tile 64x32 (4x2 wmma frags).
// Next stage's GMEM loads are issued into registers before the compute block.
#define W_PAD 40

__global__ __launch_bounds__(256) void gemm_wmma(
    const __nv_bfloat16* __restrict__ Ah, const __nv_bfloat16* __restrict__ Al,
    const __nv_bfloat16* __restrict__ Bh, const __nv_bfloat16* __restrict__ Bl,
    float* __restrict__ C, int M, int N, int K)
{
    __shared__ __nv_bfloat16 sAh[128 * W_PAD];
    __shared__ __nv_bfloat16 sAl[128 * W_PAD];
    __shared__ __nv_bfloat16 sBh[128 * W_PAD];
    __shared__ __nv_bfloat16 sBl[128 * W_PAD];

    const int tid = threadIdx.x;
    const int wid = tid >> 5;
    const int wm = wid >> 2;      // 0..1
    const int wn = wid & 3;       // 0..3
    const int m0 = blockIdx.y * 128;
    const int n0 = blockIdx.x * 128;

    const int lrow0 = tid >> 2;          // rows 0..63 (+64 for second half)
    const int lcol  = (tid & 3) * 8;     // cols 0,8,16,24

    int4 rAh[2], rAl[2], rBh[2], rBl[2];

    wmma::fragment<wmma::accumulator, 16, 16, 16, float> acc[4][2];
#pragma unroll
    for (int i = 0; i < 4; i++)
#pragma unroll
        for (int j = 0; j < 2; j++)
            wmma::fill_fragment(acc[i][j], 0.0f);

    const int NK = K >> 5;   // BK = 32

    // ---- load stage 0 into registers ----
#pragma unroll
    for (int hf = 0; hf < 2; hf++) {
        int row = lrow0 + hf * 64;
        const size_t ga = (size_t)(m0 + row) * K + lcol;
        const size_t gb = (size_t)(n0 + row) * K + lcol;
        rAh[hf] = *(const int4*)&Ah[ga];
        rAl[hf] = *(const int4*)&Al[ga];
        rBh[hf] = *(const int4*)&Bh[gb];
        rBl[hf] = *(const int4*)&Bl[gb];
    }

    for (int kt = 0; kt < NK; kt++) {
        __syncthreads();   // all readers of previous stage done
#pragma unroll
        for (int hf = 0; hf < 2; hf++) {
            int row = lrow0 + hf * 64;
            *(int4*)&sAh[row * W_PAD + lcol] = rAh[hf];
            *(int4*)&sAl[row * W_PAD + lcol] = rAl[hf];
            *(int4*)&sBh[row * W_PAD + lcol] = rBh[hf];
            *(int4*)&sBl[row * W_PAD + lcol] = rBl[hf];
        }
        __syncthreads();

        // ---- issue next stage's GMEM loads; latency hides under wmma ----
        if (kt + 1 < NK) {
            const int koff = (kt + 1) << 5;
#pragma unroll
            for (int hf = 0; hf < 2; hf++) {
                int row = lrow0 + hf * 64;
                const size_t ga = (size_t)(m0 + row) * K + koff + lcol;
                const size_t gb = (size_t)(n0 + row) * K + koff + lcol;
                rAh[hf] = *(const int4*)&Ah[ga];
                rAl[hf] = *(const int4*)&Al[ga];
                rBh[hf] = *(const int4*)&Bh[gb];
                rBl[hf] = *(const int4*)&Bl[gb];
            }
        }

#pragma unroll
        for (int kk = 0; kk < 32; kk += 16) {
            wmma::fragment<wmma::matrix_a, 16, 16, 16, __nv_bfloat16, wmma::row_major> fah[4];
            wmma::fragment<wmma::matrix_a, 16, 16, 16, __nv_bfloat16, wmma::row_major> fal[4];
            wmma::fragment<wmma::matrix_b, 16, 16, 16, __nv_bfloat16, wmma::col_major> fbh[2];
            wmma::fragment<wmma::matrix_b, 16, 16, 16, __nv_bfloat16, wmma::col_major> fbl[2];
#pragma unroll
            for (int i = 0; i < 4; i++) {
                wmma::load_matrix_sync(fah[i], &sAh[(wm * 64 + i * 16) * W_PAD + kk], W_PAD);
                wmma::load_matrix_sync(fal[i], &sAl[(wm * 64 + i * 16) * W_PAD + kk], W_PAD);
            }
#pragma unroll
            for (int j = 0; j < 2; j++) {
                wmma::load_matrix_sync(fbh[j], &sBh[(wn * 32 + j * 16) * W_PAD + kk], W_PAD);
                wmma::load_matrix_sync(fbl[j], &sBl[(wn * 32 + j * 16) * W_PAD + kk], W_PAD);
            }
#pragma unroll
            for (int i = 0; i < 4; i++) {
#pragma unroll
                for (int j = 0; j < 2; j++) {
                    wmma::mma_sync(acc[i][j], fah[i], fbh[j], acc[i][j]);
                    wmma::mma_sync(acc[i][j], fah[i], fbl[j], acc[i][j]);
                    wmma::mma_sync(acc[i][j], fal[i], fbh[j], acc[i][j]);
                }
            }
        }
    }

#pragma unroll
    for (int i = 0; i < 4; i++) {
#pragma unroll
        for (int j = 0; j < 2; j++) {
            float* dst = C + (size_t)(m0 + wm * 64 + i * 16) * N + n0 + wn * 32 + j * 16;
            wmma::store_matrix_sync(dst, acc[i][j], N, wmma::mem_row_major);
        }
    }
}

// -------- RoPE + transpose: in [B*S, nh*128] -> out [B, nh, S, 128] -------
__global__ void rope_perm(const float* __restrict__ in, float* __restrict__ outp,
                          int nheads)
{
    int idx = blockIdx.x * blockDim.x + threadIdx.x;
    int total = B_ * S_ * nheads * 64;
    if (idx >= total) return;
    int i = idx & 63;
    int t = idx >> 6;
    int h = t % nheads; t /= nheads;
    int s = t % S_;
    int b = t / S_;
    const float* src = in + ((b * S_ + s) * nheads + h) * HD;
    float x1 = src[i];
    float x2 = src[i + 64];
    float inv = __expf(-(float)i * 0.14391156831212790f);
    float ang = (float)s * inv;
    float sn, cs;
    sincosf(ang, &sn, &cs);
    float* dst = outp + ((b * nheads + h) * S_ + s) * HD;
    dst[i]      = x1 * cs - x2 * sn;
    dst[i + 64] = x2 * cs + x1 * sn;
}

// -------- V transpose: [B*S, 8*128] -> [B, 8, S, 128] ---------------------
__global__ void perm_v(const float* __restrict__ in, float* __restrict__ outp)
{
    int idx = blockIdx.x * blockDim.x + threadIdx.x;
    int total = B_ * S_ * NKV * HD;
    if (idx >= total) return;
    int d = idx & 127;
    int t = idx >> 7;
    int kh = t % NKV; t /= NKV;
    int s = t % S_;
    int b = t / S_;
    outp[((b * NKV + kh) * S_ + s) * HD + d] =
        in[((b * S_ + s) * NKV + kh) * HD + d];
}

// -------- fp32 flash attention (Round-1 verbatim) -------------------------
#define QS_STRIDE 132
#define PS_STRIDE 68
#define FLASH_SMEM_FLOATS (64*QS_STRIDE + 128*64 + 64*128 + 64*PS_STRIDE)

__global__ __launch_bounds__(256) void flash_attn(
    const float* __restrict__ q, const float* __restrict__ k,
    const float* __restrict__ v, float* __restrict__ outp)
{
    const int qt = blockIdx.x;
    const int bh = blockIdx.y;
    const int b  = bh >> 5;
    const int h  = bh & 31;
    const int kh = h >> 2;
    const int q0 = qt * 64;

    extern __shared__ float sm[];
    float* Qs = sm;
    float* Kt = Qs + 64 * QS_STRIDE;
    float* Vs = Kt + 128 * 64;
    float* Ps = Vs + 64 * 128;

    const int tid = threadIdx.x;
    const int r = tid >> 2;
    const int g = tid & 3;
    const float scale = 0.08838834764831845f;

    const float* qb = q + ((b * NH + h) * S_ + q0) * HD;
#pragma unroll
    for (int p = 0; p < 8; p++) {
        int idx = tid + p * 256;
        int row = idx >> 5;
        int cc = (idx & 31) * 4;
        float4 f = *(const float4*)&qb[row * HD + cc];
        Qs[row * QS_STRIDE + cc + 0] = f.x * scale;
        Qs[row * QS_STRIDE + cc + 1] = f.y * scale;
        Qs[row * QS_STRIDE + cc + 2] = f.z * scale;
        Qs[row * QS_STRIDE + cc + 3] = f.w * scale;
    }

    float O[32];
#pragma unroll
    for (int i = 0; i < 32; i++) O[i] = 0.f;
    float mrow = -1e30f, lrow = 0.f;

    const float* kbase = k + (b * NKV + kh) * S_ * HD;
    const float* vbase = v + (b * NKV + kh) * S_ * HD;
    const int nkb = qt + 1;

    for (int kb = 0; kb < nkb; kb++) {
        __syncthreads();
        const float* kp = kbase + kb * 64 * HD;
        const float* vp = vbase + kb * 64 * HD;
#pragma unroll
        for (int p = 0; p < 8; p++) {
            int idx = tid + p * 256;
            int row = idx >> 5;
            int cc = (idx & 31) * 4;
            float4 f = *(const float4*)&kp[row * HD + cc];
            Kt[(cc + 0) * 64 + row] = f.x;
            Kt[(cc + 1) * 64 + row] = f.y;
            Kt[(cc + 2) * 64 + row] = f.z;
            Kt[(cc + 3) * 64 + row] = f.w;
            float4 fv = *(const float4*)&vp[row * HD + cc];
            *(float4*)&Vs[row * HD + cc] = fv;
        }
        __syncthreads();

        float s[16];
#pragma unroll
        for (int jj = 0; jj < 16; jj++) s[jj] = 0.f;
#pragma unroll 1
        for (int dc = 0; dc < 8; dc++) {
            float qr[16];
            *(float4*)&qr[0]  = *(const float4*)&Qs[r * QS_STRIDE + dc * 16 + 0];
            *(float4*)&qr[4]  = *(const float4*)&Qs[r * QS_STRIDE + dc * 16 + 4];
            *(float4*)&qr[8]  = *(const float4*)&Qs[r * QS_STRIDE + dc * 16 + 8];
            *(float4*)&qr[12] = *(const float4*)&Qs[r * QS_STRIDE + dc * 16 + 12];
#pragma unroll
            for (int dd = 0; dd < 16; dd++) {
                const int d = dc * 16 + dd;
                const float* krow = &Kt[d * 64 + g * 16];
                float4 k0 = *(const float4*)&krow[0];
                float4 k1 = *(const float4*)&krow[4];
                float4 k2 = *(const float4*)&krow[8];
                float4 k3 = *(const float4*)&krow[12];
                float qv = qr[dd];
                s[0]  = fmaf(qv, k0.x, s[0]);  s[1]  = fmaf(qv, k0.y, s[1]);
                s[2]  = fmaf(qv, k0.z, s[2]);  s[3]  = fmaf(qv, k0.w, s[3]);
                s[4]  = fmaf(qv, k1.x, s[4]);  s[5]  = fmaf(qv, k1.y, s[5]);
                s[6]  = fmaf(qv, k1.z, s[6]);  s[7]  = fmaf(qv, k1.w, s[7]);
                s[8]  = fmaf(qv, k2.x, s[8]);  s[9]  = fmaf(qv, k2.y, s[9]);
                s[10] = fmaf(qv, k2.z, s[10]); s[11] = fmaf(qv, k2.w, s[11]);
                s[12] = fmaf(qv, k3.x, s[12]); s[13] = fmaf(qv, k3.y, s[13]);
                s[14] = fmaf(qv, k3.z, s[14]); s[15] = fmaf(qv, k3.w, s[15]);
            }
        }

        if (kb == qt) {
            const int qi = q0 + r;
#pragma unroll
            for (int jj = 0; jj < 16; jj++) {
                int kj = kb * 64 + g * 16 + jj;
                if (kj > qi) s[jj] = -1e30f;
            }
        }

        float mx = s[0];
#pragma unroll
        for (int jj = 1; jj < 16; jj++) mx = fmaxf(mx, s[jj]);
        mx = fmaxf(mx, __shfl_xor_sync(0xffffffffu, mx, 1));
        mx = fmaxf(mx, __shfl_xor_sync(0xffffffffu, mx, 2));
        float mnew = fmaxf(mrow, mx);
        float corr = __expf(mrow - mnew);
        float rs = 0.f;
#pragma unroll
        for (int jj = 0; jj < 16; jj++) {
            float pv = __expf(s[jj] - mnew);
            s[jj] = pv;
            rs += pv;
        }
        rs += __shfl_xor_sync(0xffffffffu, rs, 1);
        rs += __shfl_xor_sync(0xffffffffu, rs, 2);
        lrow = lrow * corr + rs;
        mrow = mnew;
#pragma unroll
        for (int i = 0; i < 32; i++) O[i] *= corr;

        *(float4*)&Ps[r * PS_STRIDE + g * 16 + 0]  = make_float4(s[0], s[1], s[2], s[3]);
        *(float4*)&Ps[r * PS_STRIDE + g * 16 + 4]  = make_float4(s[4], s[5], s[6], s[7]);
        *(float4*)&Ps[r * PS_STRIDE + g * 16 + 8]  = make_float4(s[8], s[9], s[10], s[11]);
        *(float4*)&Ps[r * PS_STRIDE + g * 16 + 12] = make_float4(s[12], s[13], s[14], s[15]);
        __syncwarp();

#pragma unroll 4
        for (int jj = 0; jj < 64; jj++) {
            float pv = Ps[r * PS_STRIDE + jj];
            const float* vrow = &Vs[jj * HD + g * 4];
#pragma unroll
            for (int ii = 0; ii < 8; ii++) {
                float4 vv = *(const float4*)&vrow[ii * 16];
                O[ii * 4 + 0] = fmaf(pv, vv.x, O[ii * 4 + 0]);
                O[ii * 4 + 1] = fmaf(pv, vv.y, O[ii * 4 + 1]);
                O[ii * 4 + 2] = fmaf(pv, vv.z, O[ii * 4 + 2]);
                O[ii * 4 + 3] = fmaf(pv, vv.w, O[ii * 4 + 3]);
            }
        }
    }

    const float inv = 1.0f / lrow;
    float* ob = outp + (b * S_ + q0 + r) * HID + h * HD + g * 4;
#pragma unroll
    for (int ii = 0; ii < 8; ii++) {
        float4 vv = make_float4(O[ii * 4 + 0] * inv, O[ii * 4 + 1] * inv,
                                O[ii * 4 + 2] * inv, O[ii * 4 + 3] * inv);
        *(float4*)&ob[ii * 16] = vv;
    }
}

// ---------------- launch ---------------------------------------------------
extern "C" void kernel_launch(void* const* d_in, const int* in_sizes, int n_in,
                              void* d_out, int out_size)
{
    (void)in_sizes; (void)n_in; (void)out_size;
    const float* x  = (const float*)d_in[0];
    const float* wq = (const float*)d_in[2];
    const float* wk = (const float*)d_in[3];
    const float* wv = (const float*)d_in[4];
    const float* wo = (const float*)d_in[5];
    float* out = (float*)d_out;

    float *qlin, *klin, *vlin, *qb, *kb, *vb, *attn;
    cudaGetSymbolAddress((void**)&qlin, g_qlin);
    cudaGetSymbolAddress((void**)&klin, g_klin);
    cudaGetSymbolAddress((void**)&vlin, g_vlin);
    cudaGetSymbolAddress((void**)&qb,   g_q);
    cudaGetSymbolAddress((void**)&kb,   g_k);
    cudaGetSymbolAddress((void**)&vb,   g_v);
    cudaGetSymbolAddress((void**)&attn, g_attn);

    __nv_bfloat16 *xh, *xl, *wqh, *wql, *wkh, *wkl, *wvh, *wvl, *woh, *wol, *ah, *al;
    cudaGetSymbolAddress((void**)&xh,  g_xh);
    cudaGetSymbolAddress((void**)&xl,  g_xl);
    cudaGetSymbolAddress((void**)&wqh, g_wqh);
    cudaGetSymbolAddress((void**)&wql, g_wql);
    cudaGetSymbolAddress((void**)&wkh, g_wkh);
    cudaGetSymbolAddress((void**)&wkl, g_wkl);
    cudaGetSymbolAddress((void**)&wvh, g_wvh);
    cudaGetSymbolAddress((void**)&wvl, g_wvl);
    cudaGetSymbolAddress((void**)&woh, g_woh);
    cudaGetSymbolAddress((void**)&wol, g_wol);
    cudaGetSymbolAddress((void**)&ah,  g_ah);
    cudaGetSymbolAddress((void**)&al,  g_al);

    const int M = B_ * S_;
    const int NKVD = NKV * HD;

    int n4 = (M * HID) / 4;
    cvt_split<<<(n4 + 255) / 256, 256>>>(x,  xh,  xl,  n4);
    cvt_split<<<(n4 + 255) / 256, 256>>>(wq, wqh, wql, n4);
    cvt_split<<<(n4 + 255) / 256, 256>>>(wo, woh, wol, n4);
    int n4s = (NKVD * HID) / 4;
    cvt_split<<<(n4s + 255) / 256, 256>>>(wk, wkh, wkl, n4s);
    cvt_split<<<(n4s + 255) / 256, 256>>>(wv, wvh, wvl, n4s);

    gemm_wmma<<<dim3(HID / 128, M / 128), 256>>>(xh, xl, wqh, wql, qlin, M, HID, HID);
    gemm_wmma<<<dim3(NKVD / 128, M / 128), 256>>>(xh, xl, wkh, wkl, klin, M, NKVD, HID);
    gemm_wmma<<<dim3(NKVD / 128, M / 128), 256>>>(xh, xl, wvh, wvl, vlin, M, NKVD, HID);

    int n1 = B_ * S_ * NH * 64;
    rope_perm<<<(n1 + 255) / 256, 256>>>(qlin, qb, NH);
    int n2 = B_ * S_ * NKV * 64;
    rope_perm<<<(n2 + 255) / 256, 256>>>(klin, kb, NKV);
    int n3 = B_ * S_ * NKV * HD;
    perm_v<<<(n3 + 255) / 256, 256>>>(vlin, vb);

    const int flash_smem = FLASH_SMEM_FLOATS * (int)sizeof(float);
    cudaFuncSetAttribute(flash_attn, cudaFuncAttributeMaxDynamicSharedMemorySize,
                         flash_smem);
    flash_attn<<<dim3(S_ / 64, B_ * NH), 256, flash_smem>>>(qb, kb, vb, attn);

    cvt_split<<<(n4 + 255) / 256, 256>>>(attn, ah, al, n4);

    gemm_wmma<<<dim3(HID / 128, M / 128), 256, 0>>>(ah, al, woh, wol, out, M, HID, HID);
}

// round 14
// speedup vs baseline: 1.5958x; 1.0962x over previous
#include <cuda_runtime.h>
#include <cuda_bf16.h>
#include <mma.h>
#include <cstdint>
#include <cstddef>
#include <math.h>

using namespace nvcuda;

#define B_   2
#define S_   2048
#define NH   32
#define NKV  8
#define HD   128
#define HID  4096

// ---------------- scratch (device globals; no allocations) ----------------
__device__ float g_qlin[B_ * S_ * HID];
__device__ float g_klin[B_ * S_ * NKV * HD];
__device__ float g_vlin[B_ * S_ * NKV * HD];
__device__ float g_q[B_ * NH * S_ * HD];
__device__ float g_k[B_ * NKV * S_ * HD];
__device__ float g_v[B_ * NKV * S_ * HD];
__device__ float g_attn[B_ * S_ * HID];

// ================= wmma bf16 split GEMM with fused fp32->hi/lo split =======
// C[M,N] = A[M,K] @ B[N,K]^T, A/B fp32 in GMEM; split into bf16 hi/lo while
// storing to smem; 3-term compensation (AhBh + AhBl + AlBh).
// Block tile 128x128x32, 4 warps (2x2), warp tile 64x64 (4x4 frags).
// __launch_bounds__(128, 2): two CTAs per SM so one CTA's tensor phase
// overlaps the other's load/sync phase.
#define W_PAD 40

__global__ __launch_bounds__(128, 2) void gemm_wmma(
    const float* __restrict__ A, const float* __restrict__ B,
    float* __restrict__ C, int M, int N, int K)
{
    __shared__ __nv_bfloat16 sAh[128 * W_PAD];
    __shared__ __nv_bfloat16 sAl[128 * W_PAD];
    __shared__ __nv_bfloat16 sBh[128 * W_PAD];
    __shared__ __nv_bfloat16 sBl[128 * W_PAD];

    const int tid = threadIdx.x;
    const int wid = tid >> 5;
    const int wm = wid >> 1;      // 0..1
    const int wn = wid & 1;       // 0..1
    const int m0 = blockIdx.y * 128;
    const int n0 = blockIdx.x * 128;

    wmma::fragment<wmma::accumulator, 16, 16, 16, float> acc[4][4];
#pragma unroll
    for (int i = 0; i < 4; i++)
#pragma unroll
        for (int j = 0; j < 4; j++)
            wmma::fill_fragment(acc[i][j], 0.0f);

    const int NK = K >> 5;   // BK = 32

    for (int kt = 0; kt < NK; kt++) {
        const int koff = kt << 5;
        __syncthreads();
        // ---- load fp32, split to bf16 hi/lo, store to smem ----
#pragma unroll
        for (int it = 0; it < 8; it++) {
            int idx = tid + it * 128;       // 0..1023 over 1024 float4 per tile
            int row = idx >> 3;
            int c4 = (idx & 7) * 4;
            float4 fa = *(const float4*)&A[(size_t)(m0 + row) * K + koff + c4];
            float4 fb = *(const float4*)&B[(size_t)(n0 + row) * K + koff + c4];

            __nv_bfloat16 ah0 = __float2bfloat16(fa.x);
            __nv_bfloat16 ah1 = __float2bfloat16(fa.y);
            __nv_bfloat16 ah2 = __float2bfloat16(fa.z);
            __nv_bfloat16 ah3 = __float2bfloat16(fa.w);
            __nv_bfloat162 ap0; ap0.x = ah0; ap0.y = ah1;
            __nv_bfloat162 ap1; ap1.x = ah2; ap1.y = ah3;
            *(__nv_bfloat162*)&sAh[row * W_PAD + c4 + 0] = ap0;
            *(__nv_bfloat162*)&sAh[row * W_PAD + c4 + 2] = ap1;
            __nv_bfloat162 al0;
            __nv_bfloat162 al1;
            al0.x = __float2bfloat16(fa.x - __bfloat162float(ah0));
            al0.y = __float2bfloat16(fa.y - __bfloat162float(ah1));
            al1.x = __float2bfloat16(fa.z - __bfloat162float(ah2));
            al1.y = __float2bfloat16(fa.w - __bfloat162float(ah3));
            *(__nv_bfloat162*)&sAl[row * W_PAD + c4 + 0] = al0;
            *(__nv_bfloat162*)&sAl[row * W_PAD + c4 + 2] = al1;

            __nv_bfloat16 bh0 = __float2bfloat16(fb.x);
            __nv_bfloat16 bh1 = __float2bfloat16(fb.y);
            __nv_bfloat16 bh2 = __float2bfloat16(fb.z);
            __nv_bfloat16 bh3 = __float2bfloat16(fb.w);
            __nv_bfloat162 bp0; bp0.x = bh0; bp0.y = bh1;
            __nv_bfloat162 bp1; bp1.x = bh2; bp1.y = bh3;
            *(__nv_bfloat162*)&sBh[row * W_PAD + c4 + 0] = bp0;
            *(__nv_bfloat162*)&sBh[row * W_PAD + c4 + 2] = bp1;
            __nv_bfloat162 bl0;
            __nv_bfloat162 bl1;
            bl0.x = __float2bfloat16(fb.x - __bfloat162float(bh0));
            bl0.y = __float2bfloat16(fb.y - __bfloat162float(bh1));
            bl1.x = __float2bfloat16(fb.z - __bfloat162float(bh2));
            bl1.y = __float2bfloat16(fb.w - __bfloat162float(bh3));
            *(__nv_bfloat162*)&sBl[row * W_PAD + c4 + 0] = bl0;
            *(__nv_bfloat162*)&sBl[row * W_PAD + c4 + 2] = bl1;
        }
        __syncthreads();

#pragma unroll
        for (int kk = 0; kk < 32; kk += 16) {
            wmma::fragment<wmma::matrix_a, 16, 16, 16, __nv_bfloat16, wmma::row_major> fah[4];
            wmma::fragment<wmma::matrix_a, 16, 16, 16, __nv_bfloat16, wmma::row_major> fal[4];
            wmma::fragment<wmma::matrix_b, 16, 16, 16, __nv_bfloat16, wmma::col_major> fbh[4];
            wmma::fragment<wmma::matrix_b, 16, 16, 16, __nv_bfloat16, wmma::col_major> fbl[4];
#pragma unroll
            for (int i = 0; i < 4; i++) {
                wmma::load_matrix_sync(fah[i], &sAh[(wm * 64 + i * 16) * W_PAD + kk], W_PAD);
                wmma::load_matrix_sync(fal[i], &sAl[(wm * 64 + i * 16) * W_PAD + kk], W_PAD);
            }
#pragma unroll
            for (int j = 0; j < 4; j++) {
                wmma::load_matrix_sync(fbh[j], &sBh[(wn * 64 + j * 16) * W_PAD + kk], W_PAD);
                wmma::load_matrix_sync(fbl[j], &sBl[(wn * 64 + j * 16) * W_PAD + kk], W_PAD);
            }
#pragma unroll
            for (int i = 0; i < 4; i++) {
#pragma unroll
                for (int j = 0; j < 4; j++) {
                    wmma::mma_sync(acc[i][j], fah[i], fbh[j], acc[i][j]);
                    wmma::mma_sync(acc[i][j], fah[i], fbl[j], acc[i][j]);
                    wmma::mma_sync(acc[i][j], fal[i], fbh[j], acc[i][j]);
                }
            }
        }
    }

#pragma unroll
    for (int i = 0; i < 4; i++) {
#pragma unroll
        for (int j = 0; j < 4; j++) {
            float* dst = C + (size_t)(m0 + wm * 64 + i * 16) * N + n0 + wn * 64 + j * 16;
            wmma::store_matrix_sync(dst, acc[i][j], N, wmma::mem_row_major);
        }
    }
}

// -------- RoPE + transpose: in [B*S, nh*128] -> out [B, nh, S, 128] -------
__global__ void rope_perm(const float* __restrict__ in, float* __restrict__ outp,
                          int nheads)
{
    int idx = blockIdx.x * blockDim.x + threadIdx.x;
    int total = B_ * S_ * nheads * 64;
    if (idx >= total) return;
    int i = idx & 63;
    int t = idx >> 6;
    int h = t % nheads; t /= nheads;
    int s = t % S_;
    int b = t / S_;
    const float* src = in + ((b * S_ + s) * nheads + h) * HD;
    float x1 = src[i];
    float x2 = src[i + 64];
    float inv = __expf(-(float)i * 0.14391156831212790f);
    float ang = (float)s * inv;
    float sn, cs;
    sincosf(ang, &sn, &cs);
    float* dst = outp + ((b * nheads + h) * S_ + s) * HD;
    dst[i]      = x1 * cs - x2 * sn;
    dst[i + 64] = x2 * cs + x1 * sn;
}

// -------- V transpose: [B*S, 8*128] -> [B, 8, S, 128] ---------------------
__global__ void perm_v(const float* __restrict__ in, float* __restrict__ outp)
{
    int idx = blockIdx.x * blockDim.x + threadIdx.x;
    int total = B_ * S_ * NKV * HD;
    if (idx >= total) return;
    int d = idx & 127;
    int t = idx >> 7;
    int kh = t % NKV; t /= NKV;
    int s = t % S_;
    int b = t / S_;
    outp[((b * NKV + kh) * S_ + s) * HD + d] =
        in[((b * S_ + s) * NKV + kh) * HD + d];
}

// -------- fp32 flash attention (Round-1 verbatim) -------------------------
#define QS_STRIDE 132
#define PS_STRIDE 68
#define FLASH_SMEM_FLOATS (64*QS_STRIDE + 128*64 + 64*128 + 64*PS_STRIDE)

__global__ __launch_bounds__(256) void flash_attn(
    const float* __restrict__ q, const float* __restrict__ k,
    const float* __restrict__ v, float* __restrict__ outp)
{
    const int qt = blockIdx.x;
    const int bh = blockIdx.y;
    const int b  = bh >> 5;
    const int h  = bh & 31;
    const int kh = h >> 2;
    const int q0 = qt * 64;

    extern __shared__ float sm[];
    float* Qs = sm;
    float* Kt = Qs + 64 * QS_STRIDE;
    float* Vs = Kt + 128 * 64;
    float* Ps = Vs + 64 * 128;

    const int tid = threadIdx.x;
    const int r = tid >> 2;
    const int g = tid & 3;
    const float scale = 0.08838834764831845f;

    const float* qb = q + ((b * NH + h) * S_ + q0) * HD;
#pragma unroll
    for (int p = 0; p < 8; p++) {
        int idx = tid + p * 256;
        int row = idx >> 5;
        int cc = (idx & 31) * 4;
        float4 f = *(const float4*)&qb[row * HD + cc];
        Qs[row * QS_STRIDE + cc + 0] = f.x * scale;
        Qs[row * QS_STRIDE + cc + 1] = f.y * scale;
        Qs[row * QS_STRIDE + cc + 2] = f.z * scale;
        Qs[row * QS_STRIDE + cc + 3] = f.w * scale;
    }

    float O[32];
#pragma unroll
    for (int i = 0; i < 32; i++) O[i] = 0.f;
    float mrow = -1e30f, lrow = 0.f;

    const float* kbase = k + (b * NKV + kh) * S_ * HD;
    const float* vbase = v + (b * NKV + kh) * S_ * HD;
    const int nkb = qt + 1;

    for (int kb = 0; kb < nkb; kb++) {
        __syncthreads();
        const float* kp = kbase + kb * 64 * HD;
        const float* vp = vbase + kb * 64 * HD;
#pragma unroll
        for (int p = 0; p < 8; p++) {
            int idx = tid + p * 256;
            int row = idx >> 5;
            int cc = (idx & 31) * 4;
            float4 f = *(const float4*)&kp[row * HD + cc];
            Kt[(cc + 0) * 64 + row] = f.x;
            Kt[(cc + 1) * 64 + row] = f.y;
            Kt[(cc + 2) * 64 + row] = f.z;
            Kt[(cc + 3) * 64 + row] = f.w;
            float4 fv = *(const float4*)&vp[row * HD + cc];
            *(float4*)&Vs[row * HD + cc] = fv;
        }
        __syncthreads();

        float s[16];
#pragma unroll
        for (int jj = 0; jj < 16; jj++) s[jj] = 0.f;
#pragma unroll 1
        for (int dc = 0; dc < 8; dc++) {
            float qr[16];
            *(float4*)&qr[0]  = *(const float4*)&Qs[r * QS_STRIDE + dc * 16 + 0];
            *(float4*)&qr[4]  = *(const float4*)&Qs[r * QS_STRIDE + dc * 16 + 4];
            *(float4*)&qr[8]  = *(const float4*)&Qs[r * QS_STRIDE + dc * 16 + 8];
            *(float4*)&qr[12] = *(const float4*)&Qs[r * QS_STRIDE + dc * 16 + 12];
#pragma unroll
            for (int dd = 0; dd < 16; dd++) {
                const int d = dc * 16 + dd;
                const float* krow = &Kt[d * 64 + g * 16];
                float4 k0 = *(const float4*)&krow[0];
                float4 k1 = *(const float4*)&krow[4];
                float4 k2 = *(const float4*)&krow[8];
                float4 k3 = *(const float4*)&krow[12];
                float qv = qr[dd];
                s[0]  = fmaf(qv, k0.x, s[0]);  s[1]  = fmaf(qv, k0.y, s[1]);
                s[2]  = fmaf(qv, k0.z, s[2]);  s[3]  = fmaf(qv, k0.w, s[3]);
                s[4]  = fmaf(qv, k1.x, s[4]);  s[5]  = fmaf(qv, k1.y, s[5]);
                s[6]  = fmaf(qv, k1.z, s[6]);  s[7]  = fmaf(qv, k1.w, s[7]);
                s[8]  = fmaf(qv, k2.x, s[8]);  s[9]  = fmaf(qv, k2.y, s[9]);
                s[10] = fmaf(qv, k2.z, s[10]); s[11] = fmaf(qv, k2.w, s[11]);
                s[12] = fmaf(qv, k3.x, s[12]); s[13] = fmaf(qv, k3.y, s[13]);
                s[14] = fmaf(qv, k3.z, s[14]); s[15] = fmaf(qv, k3.w, s[15]);
            }
        }

        if (kb == qt) {
            const int qi = q0 + r;
#pragma unroll
            for (int jj = 0; jj < 16; jj++) {
                int kj = kb * 64 + g * 16 + jj;
                if (kj > qi) s[jj] = -1e30f;
            }
        }

        float mx = s[0];
#pragma unroll
        for (int jj = 1; jj < 16; jj++) mx = fmaxf(mx, s[jj]);
        mx = fmaxf(mx, __shfl_xor_sync(0xffffffffu, mx, 1));
        mx = fmaxf(mx, __shfl_xor_sync(0xffffffffu, mx, 2));
        float mnew = fmaxf(mrow, mx);
        float corr = __expf(mrow - mnew);
        float rs = 0.f;
#pragma unroll
        for (int jj = 0; jj < 16; jj++) {
            float pv = __expf(s[jj] - mnew);
            s[jj] = pv;
            rs += pv;
        }
        rs += __shfl_xor_sync(0xffffffffu, rs, 1);
        rs += __shfl_xor_sync(0xffffffffu, rs, 2);
        lrow = lrow * corr + rs;
        mrow = mnew;
#pragma unroll
        for (int i = 0; i < 32; i++) O[i] *= corr;

        *(float4*)&Ps[r * PS_STRIDE + g * 16 + 0]  = make_float4(s[0], s[1], s[2], s[3]);
        *(float4*)&Ps[r * PS_STRIDE + g * 16 + 4]  = make_float4(s[4], s[5], s[6], s[7]);
        *(float4*)&Ps[r * PS_STRIDE + g * 16 + 8]  = make_float4(s[8], s[9], s[10], s[11]);
        *(float4*)&Ps[r * PS_STRIDE + g * 16 + 12] = make_float4(s[12], s[13], s[14], s[15]);
        __syncwarp();

#pragma unroll 4
        for (int jj = 0; jj < 64; jj++) {
            float pv = Ps[r * PS_STRIDE + jj];
            const float* vrow = &Vs[jj * HD + g * 4];
#pragma unroll
            for (int ii = 0; ii < 8; ii++) {
                float4 vv = *(const float4*)&vrow[ii * 16];
                O[ii * 4 + 0] = fmaf(pv, vv.x, O[ii * 4 + 0]);
                O[ii * 4 + 1] = fmaf(pv, vv.y, O[ii * 4 + 1]);
                O[ii * 4 + 2] = fmaf(pv, vv.z, O[ii * 4 + 2]);
                O[ii * 4 + 3] = fmaf(pv, vv.w, O[ii * 4 + 3]);
            }
        }
    }

    const float inv = 1.0f / lrow;
    float* ob = outp + (b * S_ + q0 + r) * HID + h * HD + g * 4;
#pragma unroll
    for (int ii = 0; ii < 8; ii++) {
        float4 vv = make_float4(O[ii * 4 + 0] * inv, O[ii * 4 + 1] * inv,
                                O[ii * 4 + 2] * inv, O[ii * 4 + 3] * inv);
        *(float4*)&ob[ii * 16] = vv;
    }
}

// ---------------- launch ---------------------------------------------------
extern "C" void kernel_launch(void* const* d_in, const int* in_sizes, int n_in,
                              void* d_out, int out_size)
{
    (void)in_sizes; (void)n_in; (void)out_size;
    const float* x  = (const float*)d_in[0];
    const float* wq = (const float*)d_in[2];
    const float* wk = (const float*)d_in[3];
    const float* wv = (const float*)d_in[4];
    const float* wo = (const float*)d_in[5];
    float* out = (float*)d_out;

    float *qlin, *klin, *vlin, *qb, *kb, *vb, *attn;
    cudaGetSymbolAddress((void**)&qlin, g_qlin);
    cudaGetSymbolAddress((void**)&klin, g_klin);
    cudaGetSymbolAddress((void**)&vlin, g_vlin);
    cudaGetSymbolAddress((void**)&qb,   g_q);
    cudaGetSymbolAddress((void**)&kb,   g_k);
    cudaGetSymbolAddress((void**)&vb,   g_v);
    cudaGetSymbolAddress((void**)&attn, g_attn);

    const int M = B_ * S_;
    const int NKVD = NKV * HD;

    // projections (fp32 in, split fused inside the GEMM)
    gemm_wmma<<<dim3(HID / 128, M / 128), 128>>>(x, wq, qlin, M, HID, HID);
    gemm_wmma<<<dim3(NKVD / 128, M / 128), 128>>>(x, wk, klin, M, NKVD, HID);
    gemm_wmma<<<dim3(NKVD / 128, M / 128), 128>>>(x, wv, vlin, M, NKVD, HID);

    int n1 = B_ * S_ * NH * 64;
    rope_perm<<<(n1 + 255) / 256, 256>>>(qlin, qb, NH);
    int n2 = B_ * S_ * NKV * 64;
    rope_perm<<<(n2 + 255) / 256, 256>>>(klin, kb, NKV);
    int n3 = B_ * S_ * NKV * HD;
    perm_v<<<(n3 + 255) / 256, 256>>>(vlin, vb);

    const int flash_smem = FLASH_SMEM_FLOATS * (int)sizeof(float);
    cudaFuncSetAttribute(flash_attn, cudaFuncAttributeMaxDynamicSharedMemorySize,
                         flash_smem);
    flash_attn<<<dim3(S_ / 64, B_ * NH), 256, flash_smem>>>(qb, kb, vb, attn);

    // output projection
    gemm_wmma<<<dim3(HID / 128, M / 128), 128>>>(attn, wo, out, M, HID, HID);
}

// round 15
// speedup vs baseline: 2.0301x; 1.2722x over previous
#include <cuda_runtime.h>
#include <cuda_fp16.h>
#include <mma.h>
#include <cstdint>
#include <cstddef>
#include <math.h>

using namespace nvcuda;

#define B_   2
#define S_   2048
#define NH   32
#define NKV  8
#define HD   128
#define HID  4096

// ---------------- scratch (device globals; no allocations) ----------------
__device__ float g_qlin[B_ * S_ * HID];
__device__ float g_klin[B_ * S_ * NKV * HD];
__device__ float g_vlin[B_ * S_ * NKV * HD];
__device__ float g_q[B_ * NH * S_ * HD];
__device__ float g_k[B_ * NKV * S_ * HD];
__device__ float g_v[B_ * NKV * S_ * HD];
__device__ float g_attn[B_ * S_ * HID];

__device__ __half g_xf[B_ * S_ * HID];
__device__ __half g_wqf[HID * HID];
__device__ __half g_wkf[NKV * HD * HID];
__device__ __half g_wvf[NKV * HD * HID];
__device__ __half g_wof[HID * HID];
__device__ __half g_af[B_ * S_ * HID];

// ================= fp32 -> fp16 conversion =================================
__global__ void cvt_fp16(const float* __restrict__ in, __half* __restrict__ outp,
                         int n4)
{
    int i = blockIdx.x * blockDim.x + threadIdx.x;
    if (i >= n4) return;
    float4 f = ((const float4*)in)[i];
    __half2 h0 = __floats2half2_rn(f.x, f.y);
    __half2 h1 = __floats2half2_rn(f.z, f.w);
    ((__half2*)outp)[2 * i + 0] = h0;
    ((__half2*)outp)[2 * i + 1] = h1;
}

// ================= wmma fp16 GEMM (single-term) ============================
// C[M,N] = A[M,K] @ B[N,K]^T, fp16 operands, fp32 accumulate.
// Block tile 128x128x32, 4 warps (2x2), warp tile 64x64 (4x4 frags),
// __launch_bounds__(128, 2) for 2 CTAs/SM overlap.
#define W_PAD 40

__global__ __launch_bounds__(128, 2) void gemm_fp16(
    const __half* __restrict__ A, const __half* __restrict__ B,
    float* __restrict__ C, int M, int N, int K)
{
    __shared__ __half sA[128 * W_PAD];
    __shared__ __half sB[128 * W_PAD];

    const int tid = threadIdx.x;
    const int wid = tid >> 5;
    const int wm = wid >> 1;      // 0..1
    const int wn = wid & 1;       // 0..1
    const int m0 = blockIdx.y * 128;
    const int n0 = blockIdx.x * 128;

    wmma::fragment<wmma::accumulator, 16, 16, 16, float> acc[4][4];
#pragma unroll
    for (int i = 0; i < 4; i++)
#pragma unroll
        for (int j = 0; j < 4; j++)
            wmma::fill_fragment(acc[i][j], 0.0f);

    const int NK = K >> 5;   // BK = 32

    for (int kt = 0; kt < NK; kt++) {
        const int koff = kt << 5;
        __syncthreads();
        // per tile: 128 rows x 32 halfs = 8 KB = 512 int4; 128 thr -> 4 each
#pragma unroll
        for (int it = 0; it < 4; it++) {
            int idx = tid + it * 128;       // 0..511
            int row = idx >> 2;
            int c8 = (idx & 3) * 8;
            *(int4*)&sA[row * W_PAD + c8] =
                *(const int4*)&A[(size_t)(m0 + row) * K + koff + c8];
            *(int4*)&sB[row * W_PAD + c8] =
                *(const int4*)&B[(size_t)(n0 + row) * K + koff + c8];
        }
        __syncthreads();

#pragma unroll
        for (int kk = 0; kk < 32; kk += 16) {
            wmma::fragment<wmma::matrix_a, 16, 16, 16, __half, wmma::row_major> fa[4];
            wmma::fragment<wmma::matrix_b, 16, 16, 16, __half, wmma::col_major> fb[4];
#pragma unroll
            for (int i = 0; i < 4; i++)
                wmma::load_matrix_sync(fa[i], &sA[(wm * 64 + i * 16) * W_PAD + kk], W_PAD);
#pragma unroll
            for (int j = 0; j < 4; j++)
                wmma::load_matrix_sync(fb[j], &sB[(wn * 64 + j * 16) * W_PAD + kk], W_PAD);
#pragma unroll
            for (int i = 0; i < 4; i++)
#pragma unroll
                for (int j = 0; j < 4; j++)
                    wmma::mma_sync(acc[i][j], fa[i], fb[j], acc[i][j]);
        }
    }

#pragma unroll
    for (int i = 0; i < 4; i++) {
#pragma unroll
        for (int j = 0; j < 4; j++) {
            float* dst = C + (size_t)(m0 + wm * 64 + i * 16) * N + n0 + wn * 64 + j * 16;
            wmma::store_matrix_sync(dst, acc[i][j], N, wmma::mem_row_major);
        }
    }
}

// -------- RoPE + transpose: in [B*S, nh*128] -> out [B, nh, S, 128] -------
__global__ void rope_perm(const float* __restrict__ in, float* __restrict__ outp,
                          int nheads)
{
    int idx = blockIdx.x * blockDim.x + threadIdx.x;
    int total = B_ * S_ * nheads * 64;
    if (idx >= total) return;
    int i = idx & 63;
    int t = idx >> 6;
    int h = t % nheads; t /= nheads;
    int s = t % S_;
    int b = t / S_;
    const float* src = in + ((b * S_ + s) * nheads + h) * HD;
    float x1 = src[i];
    float x2 = src[i + 64];
    float inv = __expf(-(float)i * 0.14391156831212790f);
    float ang = (float)s * inv;
    float sn, cs;
    sincosf(ang, &sn, &cs);
    float* dst = outp + ((b * nheads + h) * S_ + s) * HD;
    dst[i]      = x1 * cs - x2 * sn;
    dst[i + 64] = x2 * cs + x1 * sn;
}

// -------- V transpose: [B*S, 8*128] -> [B, 8, S, 128] ---------------------
__global__ void perm_v(const float* __restrict__ in, float* __restrict__ outp)
{
    int idx = blockIdx.x * blockDim.x + threadIdx.x;
    int total = B_ * S_ * NKV * HD;
    if (idx >= total) return;
    int d = idx & 127;
    int t = idx >> 7;
    int kh = t % NKV; t /= NKV;
    int s = t % S_;
    int b = t / S_;
    outp[((b * NKV + kh) * S_ + s) * HD + d] =
        in[((b * S_ + s) * NKV + kh) * HD + d];
}

// -------- fp32 flash attention (proven) -----------------------------------
#define QS_STRIDE 132
#define PS_STRIDE 68
#define FLASH_SMEM_FLOATS (64*QS_STRIDE + 128*64 + 64*128 + 64*PS_STRIDE)

__global__ __launch_bounds__(256) void flash_attn(
    const float* __restrict__ q, const float* __restrict__ k,
    const float* __restrict__ v, float* __restrict__ outp)
{
    const int qt = blockIdx.x;
    const int bh = blockIdx.y;
    const int b  = bh >> 5;
    const int h  = bh & 31;
    const int kh = h >> 2;
    const int q0 = qt * 64;

    extern __shared__ float sm[];
    float* Qs = sm;
    float* Kt = Qs + 64 * QS_STRIDE;
    float* Vs = Kt + 128 * 64;
    float* Ps = Vs + 64 * 128;

    const int tid = threadIdx.x;
    const int r = tid >> 2;
    const int g = tid & 3;
    const float scale = 0.08838834764831845f;

    const float* qb = q + ((b * NH + h) * S_ + q0) * HD;
#pragma unroll
    for (int p = 0; p < 8; p++) {
        int idx = tid + p * 256;
        int row = idx >> 5;
        int cc = (idx & 31) * 4;
        float4 f = *(const float4*)&qb[row * HD + cc];
        Qs[row * QS_STRIDE + cc + 0] = f.x * scale;
        Qs[row * QS_STRIDE + cc + 1] = f.y * scale;
        Qs[row * QS_STRIDE + cc + 2] = f.z * scale;
        Qs[row * QS_STRIDE + cc + 3] = f.w * scale;
    }

    float O[32];
#pragma unroll
    for (int i = 0; i < 32; i++) O[i] = 0.f;
    float mrow = -1e30f, lrow = 0.f;

    const float* kbase = k + (b * NKV + kh) * S_ * HD;
    const float* vbase = v + (b * NKV + kh) * S_ * HD;
    const int nkb = qt + 1;

    for (int kb = 0; kb < nkb; kb++) {
        __syncthreads();
        const float* kp = kbase + kb * 64 * HD;
        const float* vp = vbase + kb * 64 * HD;
#pragma unroll
        for (int p = 0; p < 8; p++) {
            int idx = tid + p * 256;
            int row = idx >> 5;
            int cc = (idx & 31) * 4;
            float4 f = *(const float4*)&kp[row * HD + cc];
            Kt[(cc + 0) * 64 + row] = f.x;
            Kt[(cc + 1) * 64 + row] = f.y;
            Kt[(cc + 2) * 64 + row] = f.z;
            Kt[(cc + 3) * 64 + row] = f.w;
            float4 fv = *(const float4*)&vp[row * HD + cc];
            *(float4*)&Vs[row * HD + cc] = fv;
        }
        __syncthreads();

        float s[16];
#pragma unroll
        for (int jj = 0; jj < 16; jj++) s[jj] = 0.f;
#pragma unroll 1
        for (int dc = 0; dc < 8; dc++) {
            float qr[16];
            *(float4*)&qr[0]  = *(const float4*)&Qs[r * QS_STRIDE + dc * 16 + 0];
            *(float4*)&qr[4]  = *(const float4*)&Qs[r * QS_STRIDE + dc * 16 + 4];
            *(float4*)&qr[8]  = *(const float4*)&Qs[r * QS_STRIDE + dc * 16 + 8];
            *(float4*)&qr[12] = *(const float4*)&Qs[r * QS_STRIDE + dc * 16 + 12];
#pragma unroll
            for (int dd = 0; dd < 16; dd++) {
                const int d = dc * 16 + dd;
                const float* krow = &Kt[d * 64 + g * 16];
                float4 k0 = *(const float4*)&krow[0];
                float4 k1 = *(const float4*)&krow[4];
                float4 k2 = *(const float4*)&krow[8];
                float4 k3 = *(const float4*)&krow[12];
                float qv = qr[dd];
                s[0]  = fmaf(qv, k0.x, s[0]);  s[1]  = fmaf(qv, k0.y, s[1]);
                s[2]  = fmaf(qv, k0.z, s[2]);  s[3]  = fmaf(qv, k0.w, s[3]);
                s[4]  = fmaf(qv, k1.x, s[4]);  s[5]  = fmaf(qv, k1.y, s[5]);
                s[6]  = fmaf(qv, k1.z, s[6]);  s[7]  = fmaf(qv, k1.w, s[7]);
                s[8]  = fmaf(qv, k2.x, s[8]);  s[9]  = fmaf(qv, k2.y, s[9]);
                s[10] = fmaf(qv, k2.z, s[10]); s[11] = fmaf(qv, k2.w, s[11]);
                s[12] = fmaf(qv, k3.x, s[12]); s[13] = fmaf(qv, k3.y, s[13]);
                s[14] = fmaf(qv, k3.z, s[14]); s[15] = fmaf(qv, k3.w, s[15]);
            }
        }

        if (kb == qt) {
            const int qi = q0 + r;
#pragma unroll
            for (int jj = 0; jj < 16; jj++) {
                int kj = kb * 64 + g * 16 + jj;
                if (kj > qi) s[jj] = -1e30f;
            }
        }

        float mx = s[0];
#pragma unroll
        for (int jj = 1; jj < 16; jj++) mx = fmaxf(mx, s[jj]);
        mx = fmaxf(mx, __shfl_xor_sync(0xffffffffu, mx, 1));
        mx = fmaxf(mx, __shfl_xor_sync(0xffffffffu, mx, 2));
        float mnew = fmaxf(mrow, mx);
        float corr = __expf(mrow - mnew);
        float rs = 0.f;
#pragma unroll
        for (int jj = 0; jj < 16; jj++) {
            float pv = __expf(s[jj] - mnew);
            s[jj] = pv;
            rs += pv;
        }
        rs += __shfl_xor_sync(0xffffffffu, rs, 1);
        rs += __shfl_xor_sync(0xffffffffu, rs, 2);
        lrow = lrow * corr + rs;
        mrow = mnew;
#pragma unroll
        for (int i = 0; i < 32; i++) O[i] *= corr;

        *(float4*)&Ps[r * PS_STRIDE + g * 16 + 0]  = make_float4(s[0], s[1], s[2], s[3]);
        *(float4*)&Ps[r * PS_STRIDE + g * 16 + 4]  = make_float4(s[4], s[5], s[6], s[7]);
        *(float4*)&Ps[r * PS_STRIDE + g * 16 + 8]  = make_float4(s[8], s[9], s[10], s[11]);
        *(float4*)&Ps[r * PS_STRIDE + g * 16 + 12] = make_float4(s[12], s[13], s[14], s[15]);
        __syncwarp();

#pragma unroll 4
        for (int jj = 0; jj < 64; jj++) {
            float pv = Ps[r * PS_STRIDE + jj];
            const float* vrow = &Vs[jj * HD + g * 4];
#pragma unroll
            for (int ii = 0; ii < 8; ii++) {
                float4 vv = *(const float4*)&vrow[ii * 16];
                O[ii * 4 + 0] = fmaf(pv, vv.x, O[ii * 4 + 0]);
                O[ii * 4 + 1] = fmaf(pv, vv.y, O[ii * 4 + 1]);
                O[ii * 4 + 2] = fmaf(pv, vv.z, O[ii * 4 + 2]);
                O[ii * 4 + 3] = fmaf(pv, vv.w, O[ii * 4 + 3]);
            }
        }
    }

    const float inv = 1.0f / lrow;
    float* ob = outp + (b * S_ + q0 + r) * HID + h * HD + g * 4;
#pragma unroll
    for (int ii = 0; ii < 8; ii++) {
        float4 vv = make_float4(O[ii * 4 + 0] * inv, O[ii * 4 + 1] * inv,
                                O[ii * 4 + 2] * inv, O[ii * 4 + 3] * inv);
        *(float4*)&ob[ii * 16] = vv;
    }
}

// ---------------- launch ---------------------------------------------------
extern "C" void kernel_launch(void* const* d_in, const int* in_sizes, int n_in,
                              void* d_out, int out_size)
{
    (void)in_sizes; (void)n_in; (void)out_size;
    const float* x  = (const float*)d_in[0];
    const float* wq = (const float*)d_in[2];
    const float* wk = (const float*)d_in[3];
    const float* wv = (const float*)d_in[4];
    const float* wo = (const float*)d_in[5];
    float* out = (float*)d_out;

    float *qlin, *klin, *vlin, *qb, *kb, *vb, *attn;
    cudaGetSymbolAddress((void**)&qlin, g_qlin);
    cudaGetSymbolAddress((void**)&klin, g_klin);
    cudaGetSymbolAddress((void**)&vlin, g_vlin);
    cudaGetSymbolAddress((void**)&qb,   g_q);
    cudaGetSymbolAddress((void**)&kb,   g_k);
    cudaGetSymbolAddress((void**)&vb,   g_v);
    cudaGetSymbolAddress((void**)&attn, g_attn);

    __half *xf, *wqf, *wkf, *wvf, *wof, *af;
    cudaGetSymbolAddress((void**)&xf,  g_xf);
    cudaGetSymbolAddress((void**)&wqf, g_wqf);
    cudaGetSymbolAddress((void**)&wkf, g_wkf);
    cudaGetSymbolAddress((void**)&wvf, g_wvf);
    cudaGetSymbolAddress((void**)&wof, g_wof);
    cudaGetSymbolAddress((void**)&af,  g_af);

    const int M = B_ * S_;
    const int NKVD = NKV * HD;

    // one-time fp32 -> fp16 conversions
    int n4 = (M * HID) / 4;
    cvt_fp16<<<(n4 + 255) / 256, 256>>>(x,  xf,  n4);
    cvt_fp16<<<(n4 + 255) / 256, 256>>>(wq, wqf, n4);
    cvt_fp16<<<(n4 + 255) / 256, 256>>>(wo, wof, n4);
    int n4s = (NKVD * HID) / 4;
    cvt_fp16<<<(n4s + 255) / 256, 256>>>(wk, wkf, n4s);
    cvt_fp16<<<(n4s + 255) / 256, 256>>>(wv, wvf, n4s);

    // projections (fp16 single-term, fp32 accumulate)
    gemm_fp16<<<dim3(HID / 128, M / 128), 128>>>(xf, wqf, qlin, M, HID, HID);
    gemm_fp16<<<dim3(NKVD / 128, M / 128), 128>>>(xf, wkf, klin, M, NKVD, HID);
    gemm_fp16<<<dim3(NKVD / 128, M / 128), 128>>>(xf, wvf, vlin, M, NKVD, HID);

    int n1 = B_ * S_ * NH * 64;
    rope_perm<<<(n1 + 255) / 256, 256>>>(qlin, qb, NH);
    int n2 = B_ * S_ * NKV * 64;
    rope_perm<<<(n2 + 255) / 256, 256>>>(klin, kb, NKV);
    int n3 = B_ * S_ * NKV * HD;
    perm_v<<<(n3 + 255) / 256, 256>>>(vlin, vb);

    const int flash_smem = FLASH_SMEM_FLOATS * (int)sizeof(float);
    cudaFuncSetAttribute(flash_attn, cudaFuncAttributeMaxDynamicSharedMemorySize,
                         flash_smem);
    flash_attn<<<dim3(S_ / 64, B_ * NH), 256, flash_smem>>>(qb, kb, vb, attn);

    // output projection
    cvt_fp16<<<(n4 + 255) / 256, 256>>>(attn, af, n4);
    gemm_fp16<<<dim3(HID / 128, M / 128), 128>>>(af, wof, out, M, HID, HID);
}